// round 9
// baseline (speedup 1.0000x reference)
#include <cuda_runtime.h>
#include <stdint.h>

#define BATCH 32
#define T 2048
#define BUCKETS 4000000ULL
#define NTOT (BATCH * T)
#define VOCAB 1024

__constant__ unsigned long long c_primes[8] = {
    2654435761ULL, 2246822519ULL, 3266489917ULL, 2028178513ULL,
    1220703125ULL, 1610612741ULL, 805306457ULL,  402653189ULL
};

// tab0 is reachable at only VOCAB=1024 rows: k0 = (tok * P0) % BUCKETS with
// tok in [0,1024). Pack those rows into a 16KB scratch, indexed by token.
__device__ float4 g_tab0[VOCAB];

__global__ void pack_tab0_kernel(const float4* __restrict__ tab0)
{
    int v = blockIdx.x * 256 + threadIdx.x;   // 4 blocks x 256
    unsigned int k = (unsigned int)(((unsigned long long)v * 2654435761ULL) % BUCKETS);
    g_tab0[v] = __ldg(&tab0[k]);
}

// 256 threads/block, 2 threads/position, 128 positions/block -> 512 blocks.
__global__ __launch_bounds__(256)
void pyramid_kernel(const unsigned int* __restrict__ tok32,
                    const float4* __restrict__ tab1,
                    const float4* __restrict__ tab2,
                    const float4* __restrict__ tab3,
                    const float* __restrict__ cond_w,
                    float4* __restrict__ out)
{
    __shared__ float w[64];
    __shared__ unsigned int s_tok[8 + 128];
    __shared__ int s_shift;
    __shared__ float4 s_tab0[VOCAB];          // 16KB packed tab0

    const int tid = threadIdx.x;

    // contiguous 16KB copy of packed tab0 (hot in L2; 4 independent loads)
#pragma unroll
    for (int i = 0; i < 4; i++)
        s_tab0[tid + 256 * i] = g_tab0[tid + 256 * i];

    if (tid < 64) w[tid] = cond_w[tid];
    if (tid < 32) {
        // dtype detect: int64 tokens (<1024) have all odd 32-bit words zero
        unsigned int v = tok32[1 + 2 * tid];
        unsigned int bal = __ballot_sync(0xffffffffu, v != 0u);
        if (tid == 0) s_shift = (bal == 0u) ? 1 : 0;   // 1 => int64 stride-2
    }
    __syncthreads();

    const int shift = s_shift;
    const int B0 = blockIdx.x * 128;        // first global position of block
    const int b  = B0 >> 11;                // T = 2048
    const int t0 = B0 & (T - 1);
    const unsigned int* row = tok32 + ((size_t)b * T << shift);

    // stage tokens [t0-8, t0+128)
    if (tid < 136) {
        int t = t0 + tid - 8;
        s_tok[tid] = (t >= 0) ? row[(size_t)t << shift] : 0u;
    }
    __syncthreads();

    const int j = tid >> 1;       // local position
    const int p = tid & 1;        // 0 -> e0/e2, 1 -> e1/e3

    // rolling XOR-hash; window-w key is the prefix after w terms
    unsigned long long h = 0ULL, h1x, h2x, h3x;
#pragma unroll
    for (int i = 0; i < 8; i++) {
        unsigned long long tok = (unsigned long long)s_tok[8 + j - 1 - i];
        h ^= tok * c_primes[i];
        if (i == 1) h1x = h;
        if (i == 3) h2x = h;
        if (i == 7) h3x = h;
    }
    unsigned int klong_pre = (unsigned int)((p ? h3x : h2x) % BUCKETS);

    // short embedding: p=0 from smem-packed tab0 (indexed by raw token),
    //                  p=1 random gather from tab1
    float4 es;
    if (p == 0) {
        es = s_tab0[s_tok[8 + j - 1]];
    } else {
        unsigned int k1 = (unsigned int)(h1x % BUCKETS);
        es = __ldg(&tab1[k1]);
    }

    // exchange with pair lane (xor 1)
    float4 eo;
    eo.x = __shfl_xor_sync(0xffffffffu, es.x, 1);
    eo.y = __shfl_xor_sync(0xffffffffu, es.y, 1);
    eo.z = __shfl_xor_sync(0xffffffffu, es.z, 1);
    eo.w = __shfl_xor_sync(0xffffffffu, es.w, 1);

    // cat = [e0, e1] regardless of parity
    float cat[8];
    if (p == 0) {
        cat[0] = es.x; cat[1] = es.y; cat[2] = es.z; cat[3] = es.w;
        cat[4] = eo.x; cat[5] = eo.y; cat[6] = eo.z; cat[7] = eo.w;
    } else {
        cat[0] = eo.x; cat[1] = eo.y; cat[2] = eo.z; cat[3] = eo.w;
        cat[4] = es.x; cat[5] = es.y; cat[6] = es.z; cat[7] = es.w;
    }

    // sign-LSH: sequential fma chain matches reference fp order;
    // both lanes compute the identical deterministic result
    unsigned long long ck = 0ULL;
#pragma unroll
    for (int o = 0; o < 8; o++) {
        float acc = 0.0f;
#pragma unroll
        for (int d = 0; d < 8; d++)
            acc = fmaf(cat[d], w[o * 8 + d], acc);
        if (acc > 0.0f) ck ^= c_primes[o];
    }

    unsigned int kk = (unsigned int)(((unsigned long long)klong_pre ^ ck) % BUCKETS);

    // one long gather per thread
    const float4* tlong = p ? tab3 : tab2;
    float4 el = __ldg(&tlong[kk]);

    // output per position: [e0, e1, e2, e3]; streaming stores keep L2
    // capacity for the table working set
    size_t base = ((size_t)(B0 + j)) * 4;
    __stcs(&out[base + p], es);          // e0 / e1
    __stcs(&out[base + 2 + p], el);      // e2 / e3
}

extern "C" void kernel_launch(void* const* d_in, const int* in_sizes, int n_in,
                              void* d_out, int out_size)
{
    // Resolve inputs by element count:
    //   tokens = 65536, each table = 16,000,000, cond_w = 64
    const void* tokens = 0;
    const void* tabs[4] = {0, 0, 0, 0};
    const void* cw = 0;
    int nt = 0;
    for (int i = 0; i < n_in; i++) {
        if (in_sizes[i] == 64) cw = d_in[i];
        else if (in_sizes[i] == 16000000) { if (nt < 4) tabs[nt++] = d_in[i]; }
        else if (in_sizes[i] == BATCH * T) tokens = d_in[i];
    }

    pack_tab0_kernel<<<VOCAB / 256, 256>>>((const float4*)tabs[0]);
    pyramid_kernel<<<NTOT / 128, 256>>>(
        (const unsigned int*)tokens,
        (const float4*)tabs[1], (const float4*)tabs[2], (const float4*)tabs[3],
        (const float*)cw, (float4*)d_out);
}

// round 10
// speedup vs baseline: 1.2952x; 1.2952x over previous
#include <cuda_runtime.h>
#include <stdint.h>

#define BATCH 32
#define T 2048
#define BUCKETS 4000000ULL
#define NTOT (BATCH * T)

__constant__ unsigned long long c_primes[8] = {
    2654435761ULL, 2246822519ULL, 3266489917ULL, 2028178513ULL,
    1220703125ULL, 1610612741ULL, 805306457ULL,  402653189ULL
};

__device__ __forceinline__ unsigned int smem_u32(const void* p)
{
    unsigned int a;
    asm("{ .reg .u64 t; cvta.to.shared.u64 t, %1; cvt.u32.u64 %0, t; }"
        : "=r"(a) : "l"(p));
    return a;
}

// 16B async copy global->shared (LDGSTS path)
__device__ __forceinline__ void cp_async16(unsigned int dst_smem, const void* src)
{
    asm volatile("cp.async.cg.shared.global [%0], [%1], 16;"
                 :: "r"(dst_smem), "l"(src) : "memory");
}
__device__ __forceinline__ void cp_async_commit_wait()
{
    asm volatile("cp.async.commit_group;\n\tcp.async.wait_group 0;" ::: "memory");
}

// Champion config (R6): 256 threads/block, 2 threads/position, 512 blocks.
// Kernel is DRAM-random-access bound: ~190K distinct 128B table lines per
// run at ~30% HBM efficiency sets a ~9-10us cold floor; all concurrency /
// hint / staging variants measured within +-5% of this. Request count is
// irreducible (full-entropy hash keys, data-dependent LSH XOR on long keys).
__global__ __launch_bounds__(256)
void pyramid_kernel(const unsigned int* __restrict__ tok32,
                    const float4* __restrict__ tab0,
                    const float4* __restrict__ tab1,
                    const float4* __restrict__ tab2,
                    const float4* __restrict__ tab3,
                    const float* __restrict__ cond_w,
                    float4* __restrict__ out)
{
    __shared__ float w[64];
    __shared__ unsigned int s_tok[8 + 128];
    __shared__ int s_shift;
    __shared__ float4 s_es[256];   // short-gather staging
    __shared__ float4 s_el[256];   // long-gather staging

    const int tid = threadIdx.x;
    if (tid < 64) w[tid] = cond_w[tid];
    if (tid < 32) {
        // dtype detect: int64 tokens (<1024) have all odd 32-bit words zero
        unsigned int v = tok32[1 + 2 * tid];
        unsigned int bal = __ballot_sync(0xffffffffu, v != 0u);
        if (tid == 0) s_shift = (bal == 0u) ? 1 : 0;   // 1 => int64 stride-2
    }
    __syncthreads();

    const int shift = s_shift;
    const int B0 = blockIdx.x * 128;        // first global position of block
    const int b  = B0 >> 11;                // T = 2048
    const int t0 = B0 & (T - 1);
    const unsigned int* row = tok32 + ((size_t)b * T << shift);

    // stage tokens [t0-8, t0+128)
    if (tid < 136) {
        int t = t0 + tid - 8;
        s_tok[tid] = (t >= 0) ? row[(size_t)t << shift] : 0u;
    }
    __syncthreads();

    const int j = tid >> 1;       // local position
    const int p = tid & 1;        // 0 -> e0/e2, 1 -> e1/e3

    // rolling XOR-hash; window-w key is the prefix after w terms
    unsigned long long h = 0ULL, h0, h1, h2, h3;
#pragma unroll
    for (int i = 0; i < 8; i++) {
        unsigned long long tok = (unsigned long long)s_tok[8 + j - 1 - i];
        h ^= tok * c_primes[i];
        if (i == 0) h0 = h;
        if (i == 1) h1 = h;
        if (i == 3) h2 = h;
        if (i == 7) h3 = h;
    }
    unsigned int kshort = (unsigned int)((p ? h1 : h0) % BUCKETS);
    unsigned int klong_pre = (unsigned int)((p ? h3 : h2) % BUCKETS);

    // phase 1: short gather via cp.async
    const float4* tshort = p ? tab1 : tab0;
    unsigned int es_addr = smem_u32(&s_es[tid]);
    cp_async16(es_addr, &tshort[kshort]);
    cp_async_commit_wait();
    float4 es = s_es[tid];

    // exchange with pair lane (xor 1)
    float4 eo;
    eo.x = __shfl_xor_sync(0xffffffffu, es.x, 1);
    eo.y = __shfl_xor_sync(0xffffffffu, es.y, 1);
    eo.z = __shfl_xor_sync(0xffffffffu, es.z, 1);
    eo.w = __shfl_xor_sync(0xffffffffu, es.w, 1);

    // cat = [e0, e1] regardless of parity
    float cat[8];
    if (p == 0) {
        cat[0] = es.x; cat[1] = es.y; cat[2] = es.z; cat[3] = es.w;
        cat[4] = eo.x; cat[5] = eo.y; cat[6] = eo.z; cat[7] = eo.w;
    } else {
        cat[0] = eo.x; cat[1] = eo.y; cat[2] = eo.z; cat[3] = eo.w;
        cat[4] = es.x; cat[5] = es.y; cat[6] = es.z; cat[7] = es.w;
    }

    // sign-LSH: sequential fma chain matches reference fp order;
    // both lanes compute the identical deterministic result
    unsigned long long ck = 0ULL;
#pragma unroll
    for (int o = 0; o < 8; o++) {
        float acc = 0.0f;
#pragma unroll
        for (int d = 0; d < 8; d++)
            acc = fmaf(cat[d], w[o * 8 + d], acc);
        if (acc > 0.0f) ck ^= c_primes[o];
    }

    unsigned int kk = (unsigned int)(((unsigned long long)klong_pre ^ ck) % BUCKETS);

    // phase 2: long gather via cp.async
    const float4* tlong = p ? tab3 : tab2;
    unsigned int el_addr = smem_u32(&s_el[tid]);
    cp_async16(el_addr, &tlong[kk]);
    cp_async_commit_wait();
    float4 el = s_el[tid];

    // output per position: [e0, e1, e2, e3]; streaming stores keep L2
    // capacity for the table working set
    size_t base = ((size_t)(B0 + j)) * 4;
    __stcs(&out[base + p], es);          // e0 / e1
    __stcs(&out[base + 2 + p], el);      // e2 / e3
}

extern "C" void kernel_launch(void* const* d_in, const int* in_sizes, int n_in,
                              void* d_out, int out_size)
{
    // Resolve inputs by element count:
    //   tokens = 65536, each table = 16,000,000, cond_w = 64
    const void* tokens = 0;
    const void* tabs[4] = {0, 0, 0, 0};
    const void* cw = 0;
    int nt = 0;
    for (int i = 0; i < n_in; i++) {
        if (in_sizes[i] == 64) cw = d_in[i];
        else if (in_sizes[i] == 16000000) { if (nt < 4) tabs[nt++] = d_in[i]; }
        else if (in_sizes[i] == BATCH * T) tokens = d_in[i];
    }

    pyramid_kernel<<<NTOT / 128, 256>>>(
        (const unsigned int*)tokens,
        (const float4*)tabs[0], (const float4*)tabs[1],
        (const float4*)tabs[2], (const float4*)tabs[3],
        (const float*)cw, (float4*)d_out);
}